// round 12
// baseline (speedup 1.0000x reference)
#include <cuda_runtime.h>
#include <cuda_fp16.h>
#include <math.h>

// Problem constants
#define NN 50000
#define EE 800000
#define NE 850000      // EE + NN self loops
#define FIN 32
#define CDIM 16
#define DIN 48
#define CC 64
#define H0 2

// ---------------- device scratch (allocation-free rule: __device__ globals) --------
__device__ __half g_h0h[NN * 128];    // layer0 node features, fp16 [N,2,64]
__device__ float g_as0[NN * 2];
__device__ float g_ad0[NN * 2];
__device__ float g_agg0[NN * 128];    // normalized aggregated messages (fp32)
__device__ __half g_h1h[NN * 64];     // layer1 input features, fp16
__device__ float g_as1[NN];
__device__ float g_ad1[NN];
// CSR build scratch
__device__ int g_cnt[NN];
__device__ int g_off[NN + 1];
__device__ int g_cur[NN];
__device__ int g_srcs[NE];

// ---------------- CSR build: histogram of dst -------------------------------------
__global__ void khist(const int* __restrict__ ei) {
    int e = blockIdx.x * blockDim.x + threadIdx.x;
    if (e >= NE) return;
    int dst = (e < EE) ? ei[EE + e] : (e - EE);
    atomicAdd(&g_cnt[dst], 1);
}

// ---------------- CSR build: exclusive scan (single block, 1024 threads) ----------
__global__ void __launch_bounds__(1024) kscan() {
    __shared__ int spart[1024];
    const int CH = (NN + 1023) / 1024;   // 49
    int t = threadIdx.x;
    int base = t * CH;
    int sum = 0;
    for (int i = 0; i < CH; ++i) {
        int b = base + i;
        if (b < NN) sum += g_cnt[b];
    }
    spart[t] = sum;
    __syncthreads();
    for (int o = 1; o < 1024; o <<= 1) {
        int v = (t >= o) ? spart[t - o] : 0;
        __syncthreads();
        spart[t] += v;
        __syncthreads();
    }
    int run = spart[t] - sum;           // exclusive prefix of this thread's chunk
    for (int i = 0; i < CH; ++i) {
        int b = base + i;
        if (b < NN) {
            g_off[b] = run;
            g_cur[b] = run;
            run += g_cnt[b];
        }
    }
    if (t == 1023) g_off[NN] = spart[1023];
}

// ---------------- CSR build: scatter src ids --------------------------------------
__global__ void kscatter(const int* __restrict__ ei) {
    int e = blockIdx.x * blockDim.x + threadIdx.x;
    if (e >= NE) return;
    int src, dst;
    if (e < EE) { src = ei[e]; dst = ei[EE + e]; }
    else        { src = dst = e - EE; }
    int pos = atomicAdd(&g_cur[dst], 1);
    g_srcs[pos] = src;
}

// ---------------- K1: h0 = concat(base, emb[cid]) @ W0 ; alphas from acc·a ---------
// 256 threads = 8 warps: 2 nodes/iter, 4 warps per node, 1 output col per lane.
#define K1_NPB 64
__global__ void __launch_bounds__(256) k1(const float* __restrict__ x,
                                          const float* __restrict__ emb,
                                          const float* __restrict__ W0,
                                          const float* __restrict__ aS0,
                                          const float* __restrict__ aD0) {
    __shared__ __align__(16) float sIn[2][48];
    __shared__ float sRed[8][2];
    int tid = threadIdx.x, w = tid >> 5, lane = tid & 31;
    int sub = w >> 2;                 // node within pair
    int cg = w & 3;                   // column group
    int col = cg * 32 + lane;         // 0..127 (head = cg>>1)
    float wreg[48];
    #pragma unroll
    for (int k = 0; k < 48; ++k) wreg[k] = W0[k * 128 + col];
    float aS = aS0[col], aD = aD0[col];   // a_src0/a_dst0 are [2,64] = 128 contiguous

    int base = blockIdx.x * K1_NPB;
    for (int it = 0; it < K1_NPB / 2; ++it) {
        int n0 = base + it * 2;
        __syncthreads();              // sIn reuse guard
        if (tid < 96) {
            int m = tid / 48, k = tid - m * 48;
            int n = n0 + m;
            float v = 0.f;
            if (n < NN) {
                if (k < FIN) v = x[n * 33 + k];
                else {
                    int cid = (int)x[n * 33 + FIN];
                    v = emb[cid * CDIM + (k - FIN)];
                }
            }
            sIn[m][k] = v;
        }
        __syncthreads();
        int n = n0 + sub;
        float acc = 0.f;
        #pragma unroll
        for (int q = 0; q < 12; ++q) {
            float4 b4 = *(const float4*)&sIn[sub][q * 4];
            acc += b4.x * wreg[q * 4]     + b4.y * wreg[q * 4 + 1]
                 + b4.z * wreg[q * 4 + 2] + b4.w * wreg[q * 4 + 3];
        }
        float vs = acc * aS, vd = acc * aD;
        #pragma unroll
        for (int o = 16; o > 0; o >>= 1) {
            vs += __shfl_xor_sync(0xffffffffu, vs, o);
            vd += __shfl_xor_sync(0xffffffffu, vd, o);
        }
        if (n < NN) {
            g_h0h[n * 128 + col] = __float2half(acc);
            if (lane == 0) { sRed[w][0] = vs; sRed[w][1] = vd; }
        }
        __syncthreads();
        if (tid < 8) {                // 2 nodes × 2 heads × {as,ad}
            int s2 = tid >> 2, h = (tid >> 1) & 1, d = tid & 1;
            int nn = n0 + s2;
            if (nn < NN) {
                float v = sRed[s2 * 4 + h * 2][d] + sRed[s2 * 4 + h * 2 + 1][d];
                if (d == 0) g_as0[nn * 2 + h] = v;
                else        g_ad0[nn * 2 + h] = v;
            }
        }
    }
}

// ---------------- kagg0: layer0 aggregation, warp per dst node --------------------
__global__ void __launch_bounds__(256) kagg0() {
    int w = (blockIdx.x * blockDim.x + threadIdx.x) >> 5;
    if (w >= NN) return;
    int lane = threadIdx.x & 31;
    int start = g_off[w], end = g_off[w + 1];
    float2 ad = *(const float2*)(g_ad0 + w * 2);
    float4 acc = make_float4(0.f, 0.f, 0.f, 0.f);
    float d0 = 0.f, d1 = 0.f;
    for (int i = start; i < end; i += 32) {
        int idx = i + lane;
        int s = 0;
        float ex0 = 0.f, ex1 = 0.f;
        if (idx < end) {
            s = g_srcs[idx];
            float2 a = *(const float2*)(g_as0 + s * 2);
            float v0 = a.x + ad.x;  v0 = v0 > 0.f ? v0 : 0.2f * v0;
            float v1 = a.y + ad.y;  v1 = v1 > 0.f ? v1 : 0.2f * v1;
            ex0 = __expf(v0);
            ex1 = __expf(v1);
        }
        d0 += ex0;
        d1 += ex1;
        int cnt = min(32, end - i);
        #pragma unroll 4
        for (int t = 0; t < cnt; ++t) {
            int sb = __shfl_sync(0xffffffffu, s, t);
            float e0 = __shfl_sync(0xffffffffu, ex0, t);
            float e1 = __shfl_sync(0xffffffffu, ex1, t);
            float exm = (lane < 16) ? e0 : e1;   // lanes 0-15: head0, 16-31: head1
            uint2 p = *(const uint2*)(g_h0h + sb * 128 + lane * 4);
            float2 f01 = __half22float2(*(__half2*)&p.x);
            float2 f23 = __half22float2(*(__half2*)&p.y);
            acc.x += exm * f01.x;
            acc.y += exm * f01.y;
            acc.z += exm * f23.x;
            acc.w += exm * f23.y;
        }
    }
    #pragma unroll
    for (int o = 16; o > 0; o >>= 1) {
        d0 += __shfl_xor_sync(0xffffffffu, d0, o);
        d1 += __shfl_xor_sync(0xffffffffu, d1, o);
    }
    float inv = 1.0f / ((lane < 16) ? d0 : d1);
    acc.x *= inv; acc.y *= inv; acc.z *= inv; acc.w *= inv;
    *(float4*)(g_agg0 + w * 128 + lane * 4) = acc;
}

// ---------------- K4: mean heads + b0, LN, ELU, GEMM W1, alphas --------------------
// 256 threads = 8 warps: 4 nodes/iter, 2 warps per node, 1 output col per lane.
#define K4_NPB 64
__global__ void __launch_bounds__(256) k4(const float* __restrict__ b0,
                   const float* __restrict__ lng, const float* __restrict__ lnb,
                   const float* __restrict__ W1, const float* __restrict__ aS1,
                   const float* __restrict__ aD1) {
    __shared__ __align__(16) float sY[4][64];
    __shared__ float sStat[8][2];
    __shared__ float sA[8][2];
    int tid = threadIdx.x, w = tid >> 5, lane = tid & 31;
    int sub = w >> 1;                 // node within group of 4
    int col = (w & 1) * 32 + lane;    // 0..63
    float wreg[64];
    #pragma unroll
    for (int k = 0; k < 64; ++k) wreg[k] = W1[k * 64 + col];
    float aS = aS1[col], aD = aD1[col];
    float bb = b0[col], g = lng[col], be = lnb[col];

    int base = blockIdx.x * K4_NPB;
    for (int it = 0; it < K4_NPB / 4; ++it) {
        int n = base + it * 4 + sub;
        bool valid = (n < NN);
        int nn = valid ? n : 0;
        float y = 0.5f * (g_agg0[nn * 128 + col] + g_agg0[nn * 128 + 64 + col]) + bb;
        float s1 = y, s2 = y * y;
        #pragma unroll
        for (int o = 16; o > 0; o >>= 1) {
            s1 += __shfl_xor_sync(0xffffffffu, s1, o);
            s2 += __shfl_xor_sync(0xffffffffu, s2, o);
        }
        __syncthreads();              // smem reuse guard
        if (lane == 0) { sStat[w][0] = s1; sStat[w][1] = s2; }
        __syncthreads();
        int wp = w ^ 1;
        float mu = (sStat[w][0] + sStat[wp][0]) * (1.f / 64.f);
        float var = (sStat[w][1] + sStat[wp][1]) * (1.f / 64.f) - mu * mu;
        float xn = (y - mu) * rsqrtf(var + 1e-5f) * g + be;
        float ev = xn > 0.f ? xn : expm1f(xn);
        sY[sub][col] = ev;
        __syncthreads();
        float acc = 0.f;
        #pragma unroll
        for (int q = 0; q < 16; ++q) {
            float4 b4 = *(const float4*)&sY[sub][q * 4];
            acc += b4.x * wreg[q * 4]     + b4.y * wreg[q * 4 + 1]
                 + b4.z * wreg[q * 4 + 2] + b4.w * wreg[q * 4 + 3];
        }
        float vs = acc * aS, vd = acc * aD;
        #pragma unroll
        for (int o = 16; o > 0; o >>= 1) {
            vs += __shfl_xor_sync(0xffffffffu, vs, o);
            vd += __shfl_xor_sync(0xffffffffu, vd, o);
        }
        if (valid) {
            g_h1h[n * 64 + col] = __float2half(acc);
            if (lane == 0) { sA[w][0] = vs; sA[w][1] = vd; }
        }
        __syncthreads();
        if (tid < 8) {                // 4 nodes × {as,ad}
            int s2i = tid >> 1, d = tid & 1;
            int nn2 = base + it * 4 + s2i;
            if (nn2 < NN) {
                float v = sA[s2i * 2][d] + sA[s2i * 2 + 1][d];
                if (d == 0) g_as1[nn2] = v;
                else        g_ad1[nn2] = v;
            }
        }
    }
}

// ---------------- kagg1: layer1 aggregation, warp per dst node, writes out --------
__global__ void __launch_bounds__(256) kagg1(float* __restrict__ out,
                                             const float* __restrict__ b1) {
    int w = (blockIdx.x * blockDim.x + threadIdx.x) >> 5;
    if (w >= NN) return;
    int lane = threadIdx.x & 31;
    int start = g_off[w], end = g_off[w + 1];
    float ad = g_ad1[w];
    float2 acc = make_float2(0.f, 0.f);
    float den = 0.f;
    for (int i = start; i < end; i += 32) {
        int idx = i + lane;
        int s = 0;
        float ex = 0.f;
        if (idx < end) {
            s = g_srcs[idx];
            float v = g_as1[s] + ad;
            v = v > 0.f ? v : 0.2f * v;
            ex = __expf(v);
        }
        den += ex;
        int cnt = min(32, end - i);
        #pragma unroll 4
        for (int t = 0; t < cnt; ++t) {
            int sb = __shfl_sync(0xffffffffu, s, t);
            float eb = __shfl_sync(0xffffffffu, ex, t);
            __half2 hp = *(const __half2*)(g_h1h + sb * 64 + lane * 2);
            float2 f = __half22float2(hp);
            acc.x += eb * f.x;
            acc.y += eb * f.y;
        }
    }
    #pragma unroll
    for (int o = 16; o > 0; o >>= 1)
        den += __shfl_xor_sync(0xffffffffu, den, o);
    float inv = 1.0f / den;
    float2 bb = *(const float2*)(b1 + lane * 2);
    float2 r = make_float2(acc.x * inv + bb.x, acc.y * inv + bb.y);
    *(float2*)(out + w * 64 + lane * 2) = r;
}

// ---------------- launch -----------------------------------------------------------
extern "C" void kernel_launch(void* const* d_in, const int* in_sizes, int n_in,
                              void* d_out, int out_size) {
    const float* x      = (const float*)d_in[0];
    const int*   ei     = (const int*)  d_in[1];
    const float* emb    = (const float*)d_in[2];
    const float* W0     = (const float*)d_in[3];
    const float* a_src0 = (const float*)d_in[4];
    const float* a_dst0 = (const float*)d_in[5];
    const float* b0     = (const float*)d_in[6];
    const float* ln_g   = (const float*)d_in[7];
    const float* ln_b   = (const float*)d_in[8];
    const float* W1     = (const float*)d_in[9];
    const float* a_src1 = (const float*)d_in[10];
    const float* a_dst1 = (const float*)d_in[11];
    const float* b1     = (const float*)d_in[12];
    float* out = (float*)d_out;

    // CSR build (shared by both layers)
    void* cnt_addr = nullptr;
    cudaGetSymbolAddress(&cnt_addr, g_cnt);
    cudaMemsetAsync(cnt_addr, 0, NN * sizeof(int));
    khist<<<(NE + 255) / 256, 256>>>(ei);
    kscan<<<1, 1024>>>();
    kscatter<<<(NE + 255) / 256, 256>>>(ei);
    // layer 0
    k1<<<(NN + K1_NPB - 1) / K1_NPB, 256>>>(x, emb, W0, a_src0, a_dst0);
    kagg0<<<(NN * 32 + 255) / 256, 256>>>();
    // layer 1
    k4<<<(NN + K4_NPB - 1) / K4_NPB, 256>>>(b0, ln_g, ln_b, W1, a_src1, a_dst1);
    kagg1<<<(NN * 32 + 255) / 256, 256>>>(out, b1);
}

// round 13
// speedup vs baseline: 1.0015x; 1.0015x over previous
#include <cuda_runtime.h>
#include <cuda_fp16.h>
#include <math.h>

// Problem constants
#define NN 50000
#define EE 800000
#define NE 850000      // EE + NN self loops
#define FIN 32
#define CDIM 16
#define DIN 48
#define CC 64
#define H0 2

// ---------------- device scratch (allocation-free rule: __device__ globals) --------
__device__ __half g_h0h[NN * 128];    // layer0 node features, fp16 [N,2,64]
__device__ float g_as0[NN * 2];
__device__ float g_ad0[NN * 2];
__device__ float g_agg0[NN * 128];    // normalized aggregated messages (fp32)
__device__ __half g_h1h[NN * 64];     // layer1 input features, fp16
__device__ float g_as1[NN];
__device__ float g_ad1[NN];
// CSR build scratch
__device__ int g_cnt[NN];
__device__ int g_off[NN + 1];
__device__ int g_cur[NN];
__device__ int g_srcs[NE];

// ---------------- CSR build: histogram of dst -------------------------------------
__global__ void khist(const int* __restrict__ ei) {
    int e = blockIdx.x * blockDim.x + threadIdx.x;
    if (e >= NE) return;
    int dst = (e < EE) ? ei[EE + e] : (e - EE);
    atomicAdd(&g_cnt[dst], 1);
}

// ---------------- CSR build: exclusive scan (single block, 1024 threads) ----------
__global__ void __launch_bounds__(1024) kscan() {
    __shared__ int spart[1024];
    const int CH = (NN + 1023) / 1024;   // 49
    int t = threadIdx.x;
    int base = t * CH;
    int sum = 0;
    for (int i = 0; i < CH; ++i) {
        int b = base + i;
        if (b < NN) sum += g_cnt[b];
    }
    spart[t] = sum;
    __syncthreads();
    for (int o = 1; o < 1024; o <<= 1) {
        int v = (t >= o) ? spart[t - o] : 0;
        __syncthreads();
        spart[t] += v;
        __syncthreads();
    }
    int run = spart[t] - sum;           // exclusive prefix of this thread's chunk
    for (int i = 0; i < CH; ++i) {
        int b = base + i;
        if (b < NN) {
            g_off[b] = run;
            g_cur[b] = run;
            run += g_cnt[b];
        }
    }
    if (t == 1023) g_off[NN] = spart[1023];
}

// ---------------- CSR build: scatter src ids --------------------------------------
__global__ void kscatter(const int* __restrict__ ei) {
    int e = blockIdx.x * blockDim.x + threadIdx.x;
    if (e >= NE) return;
    int src, dst;
    if (e < EE) { src = ei[e]; dst = ei[EE + e]; }
    else        { src = dst = e - EE; }
    int pos = atomicAdd(&g_cur[dst], 1);
    g_srcs[pos] = src;
}

// ---------------- K1: h0 = concat(base, emb[cid]) @ W0 ; alphas from acc·a ---------
// 256 threads = 8 warps. Tile = 16 nodes staged at once; each warp owns a
// 32-column group and sweeps 8 nodes of the tile barrier-free.
#define K1_TILE 16
#define K1_NPB 128
__global__ void __launch_bounds__(256) k1(const float* __restrict__ x,
                                          const float* __restrict__ emb,
                                          const float* __restrict__ W0,
                                          const float* __restrict__ aS0,
                                          const float* __restrict__ aD0) {
    __shared__ __align__(16) float sIn[K1_TILE][52];   // 52: 16B-aligned rows
    __shared__ float sRed[K1_TILE][4][2];              // node, colgroup, {vs,vd}
    int tid = threadIdx.x, w = tid >> 5, lane = tid & 31;
    int cg = w & 3;                   // column group (head = cg>>1)
    int col = cg * 32 + lane;         // 0..127
    float wreg[48];
    #pragma unroll
    for (int k = 0; k < 48; ++k) wreg[k] = W0[k * 128 + col];
    float aS = aS0[col], aD = aD0[col];   // a_src0/a_dst0 are [2,64] = 128 contiguous

    int base = blockIdx.x * K1_NPB;
    for (int tile = 0; tile < K1_NPB / K1_TILE; ++tile) {
        int n0 = base + tile * K1_TILE;
        __syncthreads();              // sIn/sRed reuse guard
        // stage 16 nodes x 48 inputs (768 items, 3 per thread)
        #pragma unroll
        for (int r = 0; r < 3; ++r) {
            int idx = tid + r * 256;
            int m = idx / 48, k = idx - m * 48;
            int n = n0 + m;
            float v = 0.f;
            if (n < NN) {
                if (k < FIN) v = x[n * 33 + k];
                else {
                    int cid = (int)x[n * 33 + FIN];
                    v = emb[cid * CDIM + (k - FIN)];
                }
            }
            sIn[m][k] = v;
        }
        __syncthreads();
        // each warp: 8 nodes (stride 2, offset by w>>2), no barriers inside
        int m0 = w >> 2;
        #pragma unroll
        for (int i = 0; i < 8; ++i) {
            int m = m0 + i * 2;
            int n = n0 + m;
            float a0 = 0.f, a1 = 0.f, a2 = 0.f, a3 = 0.f;
            #pragma unroll
            for (int q = 0; q < 12; q += 4) {
                float4 b0 = *(const float4*)&sIn[m][q * 4];
                float4 b1 = *(const float4*)&sIn[m][q * 4 + 4];
                float4 b2 = *(const float4*)&sIn[m][q * 4 + 8];
                float4 b3 = *(const float4*)&sIn[m][q * 4 + 12];
                a0 += b0.x * wreg[q*4]    + b0.y * wreg[q*4+1]  + b0.z * wreg[q*4+2]  + b0.w * wreg[q*4+3];
                a1 += b1.x * wreg[q*4+4]  + b1.y * wreg[q*4+5]  + b1.z * wreg[q*4+6]  + b1.w * wreg[q*4+7];
                a2 += b2.x * wreg[q*4+8]  + b2.y * wreg[q*4+9]  + b2.z * wreg[q*4+10] + b2.w * wreg[q*4+11];
                a3 += b3.x * wreg[q*4+12] + b3.y * wreg[q*4+13] + b3.z * wreg[q*4+14] + b3.w * wreg[q*4+15];
            }
            float acc = (a0 + a1) + (a2 + a3);
            float vs = acc * aS, vd = acc * aD;
            #pragma unroll
            for (int o = 16; o > 0; o >>= 1) {
                vs += __shfl_xor_sync(0xffffffffu, vs, o);
                vd += __shfl_xor_sync(0xffffffffu, vd, o);
            }
            if (n < NN) {
                g_h0h[n * 128 + col] = __float2half(acc);
                if (lane == 0) { sRed[m][cg][0] = vs; sRed[m][cg][1] = vd; }
            }
        }
        __syncthreads();
        if (tid < K1_TILE * 4) {      // 16 nodes x 2 heads x {as,ad}
            int m = tid >> 2, c = tid & 3;
            int h = c >> 1, d = c & 1;
            int n = n0 + m;
            if (n < NN) {
                float v = sRed[m][h * 2][d] + sRed[m][h * 2 + 1][d];
                if (d == 0) g_as0[n * 2 + h] = v;
                else        g_ad0[n * 2 + h] = v;
            }
        }
    }
}

// ---------------- kagg0: layer0 aggregation, warp per dst node --------------------
__global__ void __launch_bounds__(256) kagg0() {
    int w = (blockIdx.x * blockDim.x + threadIdx.x) >> 5;
    if (w >= NN) return;
    int lane = threadIdx.x & 31;
    int start = g_off[w], end = g_off[w + 1];
    float2 ad = *(const float2*)(g_ad0 + w * 2);
    float4 acc = make_float4(0.f, 0.f, 0.f, 0.f);
    float d0 = 0.f, d1 = 0.f;
    for (int i = start; i < end; i += 32) {
        int idx = i + lane;
        int s = 0;
        float ex0 = 0.f, ex1 = 0.f;
        if (idx < end) {
            s = g_srcs[idx];
            float2 a = *(const float2*)(g_as0 + s * 2);
            float v0 = a.x + ad.x;  v0 = v0 > 0.f ? v0 : 0.2f * v0;
            float v1 = a.y + ad.y;  v1 = v1 > 0.f ? v1 : 0.2f * v1;
            ex0 = __expf(v0);
            ex1 = __expf(v1);
        }
        d0 += ex0;
        d1 += ex1;
        int cnt = min(32, end - i);
        #pragma unroll 4
        for (int t = 0; t < cnt; ++t) {
            int sb = __shfl_sync(0xffffffffu, s, t);
            float e0 = __shfl_sync(0xffffffffu, ex0, t);
            float e1 = __shfl_sync(0xffffffffu, ex1, t);
            float exm = (lane < 16) ? e0 : e1;   // lanes 0-15: head0, 16-31: head1
            uint2 p = *(const uint2*)(g_h0h + sb * 128 + lane * 4);
            float2 f01 = __half22float2(*(__half2*)&p.x);
            float2 f23 = __half22float2(*(__half2*)&p.y);
            acc.x += exm * f01.x;
            acc.y += exm * f01.y;
            acc.z += exm * f23.x;
            acc.w += exm * f23.y;
        }
    }
    #pragma unroll
    for (int o = 16; o > 0; o >>= 1) {
        d0 += __shfl_xor_sync(0xffffffffu, d0, o);
        d1 += __shfl_xor_sync(0xffffffffu, d1, o);
    }
    float inv = 1.0f / ((lane < 16) ? d0 : d1);
    acc.x *= inv; acc.y *= inv; acc.z *= inv; acc.w *= inv;
    *(float4*)(g_agg0 + w * 128 + lane * 4) = acc;
}

// ---------------- K4: mean heads + b0, LN, ELU, GEMM W1, alphas --------------------
// 256 threads = 8 warps: 4 nodes/iter, 2 warps per node, 1 output col per lane.
#define K4_NPB 64
__global__ void __launch_bounds__(256) k4(const float* __restrict__ b0,
                   const float* __restrict__ lng, const float* __restrict__ lnb,
                   const float* __restrict__ W1, const float* __restrict__ aS1,
                   const float* __restrict__ aD1) {
    __shared__ __align__(16) float sY[4][64];
    __shared__ float sStat[8][2];
    __shared__ float sA[8][2];
    int tid = threadIdx.x, w = tid >> 5, lane = tid & 31;
    int sub = w >> 1;                 // node within group of 4
    int col = (w & 1) * 32 + lane;    // 0..63
    float wreg[64];
    #pragma unroll
    for (int k = 0; k < 64; ++k) wreg[k] = W1[k * 64 + col];
    float aS = aS1[col], aD = aD1[col];
    float bb = b0[col], g = lng[col], be = lnb[col];

    int base = blockIdx.x * K4_NPB;
    for (int it = 0; it < K4_NPB / 4; ++it) {
        int n = base + it * 4 + sub;
        bool valid = (n < NN);
        int nn = valid ? n : 0;
        float y = 0.5f * (g_agg0[nn * 128 + col] + g_agg0[nn * 128 + 64 + col]) + bb;
        float s1 = y, s2 = y * y;
        #pragma unroll
        for (int o = 16; o > 0; o >>= 1) {
            s1 += __shfl_xor_sync(0xffffffffu, s1, o);
            s2 += __shfl_xor_sync(0xffffffffu, s2, o);
        }
        __syncthreads();              // smem reuse guard
        if (lane == 0) { sStat[w][0] = s1; sStat[w][1] = s2; }
        __syncthreads();
        int wp = w ^ 1;
        float mu = (sStat[w][0] + sStat[wp][0]) * (1.f / 64.f);
        float var = (sStat[w][1] + sStat[wp][1]) * (1.f / 64.f) - mu * mu;
        float xn = (y - mu) * rsqrtf(var + 1e-5f) * g + be;
        float ev = xn > 0.f ? xn : expm1f(xn);
        sY[sub][col] = ev;
        __syncthreads();
        float a0 = 0.f, a1 = 0.f, a2 = 0.f, a3 = 0.f;
        #pragma unroll
        for (int q = 0; q < 16; q += 4) {
            float4 b4_0 = *(const float4*)&sY[sub][q * 4];
            float4 b4_1 = *(const float4*)&sY[sub][q * 4 + 4];
            float4 b4_2 = *(const float4*)&sY[sub][q * 4 + 8];
            float4 b4_3 = *(const float4*)&sY[sub][q * 4 + 12];
            a0 += b4_0.x * wreg[q*4]    + b4_0.y * wreg[q*4+1]  + b4_0.z * wreg[q*4+2]  + b4_0.w * wreg[q*4+3];
            a1 += b4_1.x * wreg[q*4+4]  + b4_1.y * wreg[q*4+5]  + b4_1.z * wreg[q*4+6]  + b4_1.w * wreg[q*4+7];
            a2 += b4_2.x * wreg[q*4+8]  + b4_2.y * wreg[q*4+9]  + b4_2.z * wreg[q*4+10] + b4_2.w * wreg[q*4+11];
            a3 += b4_3.x * wreg[q*4+12] + b4_3.y * wreg[q*4+13] + b4_3.z * wreg[q*4+14] + b4_3.w * wreg[q*4+15];
        }
        float acc = (a0 + a1) + (a2 + a3);
        float vs = acc * aS, vd = acc * aD;
        #pragma unroll
        for (int o = 16; o > 0; o >>= 1) {
            vs += __shfl_xor_sync(0xffffffffu, vs, o);
            vd += __shfl_xor_sync(0xffffffffu, vd, o);
        }
        if (valid) {
            g_h1h[n * 64 + col] = __float2half(acc);
            if (lane == 0) { sA[w][0] = vs; sA[w][1] = vd; }
        }
        __syncthreads();
        if (tid < 8) {                // 4 nodes x {as,ad}
            int s2i = tid >> 1, d = tid & 1;
            int nn2 = base + it * 4 + s2i;
            if (nn2 < NN) {
                float v = sA[s2i * 2][d] + sA[s2i * 2 + 1][d];
                if (d == 0) g_as1[nn2] = v;
                else        g_ad1[nn2] = v;
            }
        }
    }
}

// ---------------- kagg1: layer1 aggregation, warp per dst node, writes out --------
__global__ void __launch_bounds__(256) kagg1(float* __restrict__ out,
                                             const float* __restrict__ b1) {
    int w = (blockIdx.x * blockDim.x + threadIdx.x) >> 5;
    if (w >= NN) return;
    int lane = threadIdx.x & 31;
    int start = g_off[w], end = g_off[w + 1];
    float ad = g_ad1[w];
    float2 acc = make_float2(0.f, 0.f);
    float den = 0.f;
    for (int i = start; i < end; i += 32) {
        int idx = i + lane;
        int s = 0;
        float ex = 0.f;
        if (idx < end) {
            s = g_srcs[idx];
            float v = g_as1[s] + ad;
            v = v > 0.f ? v : 0.2f * v;
            ex = __expf(v);
        }
        den += ex;
        int cnt = min(32, end - i);
        #pragma unroll 4
        for (int t = 0; t < cnt; ++t) {
            int sb = __shfl_sync(0xffffffffu, s, t);
            float eb = __shfl_sync(0xffffffffu, ex, t);
            __half2 hp = *(const __half2*)(g_h1h + sb * 64 + lane * 2);
            float2 f = __half22float2(hp);
            acc.x += eb * f.x;
            acc.y += eb * f.y;
        }
    }
    #pragma unroll
    for (int o = 16; o > 0; o >>= 1)
        den += __shfl_xor_sync(0xffffffffu, den, o);
    float inv = 1.0f / den;
    float2 bb = *(const float2*)(b1 + lane * 2);
    float2 r = make_float2(acc.x * inv + bb.x, acc.y * inv + bb.y);
    *(float2*)(out + w * 64 + lane * 2) = r;
}

// ---------------- launch -----------------------------------------------------------
extern "C" void kernel_launch(void* const* d_in, const int* in_sizes, int n_in,
                              void* d_out, int out_size) {
    const float* x      = (const float*)d_in[0];
    const int*   ei     = (const int*)  d_in[1];
    const float* emb    = (const float*)d_in[2];
    const float* W0     = (const float*)d_in[3];
    const float* a_src0 = (const float*)d_in[4];
    const float* a_dst0 = (const float*)d_in[5];
    const float* b0     = (const float*)d_in[6];
    const float* ln_g   = (const float*)d_in[7];
    const float* ln_b   = (const float*)d_in[8];
    const float* W1     = (const float*)d_in[9];
    const float* a_src1 = (const float*)d_in[10];
    const float* a_dst1 = (const float*)d_in[11];
    const float* b1     = (const float*)d_in[12];
    float* out = (float*)d_out;

    // CSR build (shared by both layers)
    void* cnt_addr = nullptr;
    cudaGetSymbolAddress(&cnt_addr, g_cnt);
    cudaMemsetAsync(cnt_addr, 0, NN * sizeof(int));
    khist<<<(NE + 255) / 256, 256>>>(ei);
    kscan<<<1, 1024>>>();
    kscatter<<<(NE + 255) / 256, 256>>>(ei);
    // layer 0
    k1<<<(NN + K1_NPB - 1) / K1_NPB, 256>>>(x, emb, W0, a_src0, a_dst0);
    kagg0<<<(NN * 32 + 255) / 256, 256>>>();
    // layer 1
    k4<<<(NN + K4_NPB - 1) / K4_NPB, 256>>>(b0, ln_g, ln_b, W1, a_src1, a_dst1);
    kagg1<<<(NN * 32 + 255) / 256, 256>>>(out, b1);
}

// round 14
// speedup vs baseline: 1.3037x; 1.3018x over previous
#include <cuda_runtime.h>
#include <cuda_fp16.h>
#include <math.h>

// Problem constants
#define NN 50000
#define EE 800000
#define NE 850000      // EE + NN self loops
#define FIN 32
#define CDIM 16
#define DIN 48
#define CC 64
#define H0 2

// ---------------- device scratch (allocation-free rule: __device__ globals) --------
__device__ __half g_h0h[NN * 128];    // layer0 node features, fp16 [N,2,64]
__device__ float g_as0[NN * 2];
__device__ float g_ad0[NN * 2];
__device__ float g_agg0[NN * 128];    // normalized aggregated messages (fp32)
__device__ __half g_h1h[NN * 64];     // layer1 input features, fp16
__device__ float g_as1[NN];
__device__ float g_ad1[NN];
// CSR build scratch
__device__ int g_cnt[NN];
__device__ int g_off[NN + 1];
__device__ int g_cur[NN];
__device__ int g_srcs[NE];

__device__ __forceinline__ unsigned h2u(__half2 v) { return *(unsigned*)&v; }

// ---------------- CSR build: histogram of dst -------------------------------------
__global__ void khist(const int* __restrict__ ei) {
    int e = blockIdx.x * blockDim.x + threadIdx.x;
    if (e >= NE) return;
    int dst = (e < EE) ? ei[EE + e] : (e - EE);
    atomicAdd(&g_cnt[dst], 1);
}

// ---------------- CSR build: exclusive scan (single block, 1024 threads) ----------
__global__ void __launch_bounds__(1024) kscan() {
    __shared__ int spart[1024];
    const int CH = (NN + 1023) / 1024;   // 49
    int t = threadIdx.x;
    int base = t * CH;
    int sum = 0;
    for (int i = 0; i < CH; ++i) {
        int b = base + i;
        if (b < NN) sum += g_cnt[b];
    }
    spart[t] = sum;
    __syncthreads();
    for (int o = 1; o < 1024; o <<= 1) {
        int v = (t >= o) ? spart[t - o] : 0;
        __syncthreads();
        spart[t] += v;
        __syncthreads();
    }
    int run = spart[t] - sum;           // exclusive prefix of this thread's chunk
    for (int i = 0; i < CH; ++i) {
        int b = base + i;
        if (b < NN) {
            g_off[b] = run;
            g_cur[b] = run;
            run += g_cnt[b];
        }
    }
    if (t == 1023) g_off[NN] = spart[1023];
}

// ---------------- CSR build: scatter src ids --------------------------------------
__global__ void kscatter(const int* __restrict__ ei) {
    int e = blockIdx.x * blockDim.x + threadIdx.x;
    if (e >= NE) return;
    int src, dst;
    if (e < EE) { src = ei[e]; dst = ei[EE + e]; }
    else        { src = dst = e - EE; }
    int pos = atomicAdd(&g_cur[dst], 1);
    g_srcs[pos] = src;
}

// ---------------- k1g: tiled GEMM  h0 = concat(base,emb) @ W0  + alpha epilogue ----
// Block: 256 thr, tile 64 nodes x 128 cols. Thread: 4 nodes x 8 cols.
// c = tid%16 -> cols c*8..c*8+7 ; rm = tid/16 -> nodes rm*4..rm*4+3.
#define G1_M 64
__global__ void __launch_bounds__(256) k1g(const float* __restrict__ x,
                                           const float* __restrict__ emb,
                                           const float* __restrict__ W0,
                                           const float* __restrict__ aS0,
                                           const float* __restrict__ aD0) {
    __shared__ float sW[48][128];     // 24 KB
    __shared__ float sXT[48][65];     // 12.2 KB, transposed inputs
    int tid = threadIdx.x;
    int c = tid & 15, rm = tid >> 4;
    int base = blockIdx.x * G1_M;

    // stage W0 (48x128, row-major) -> sW
    {
        float4* dstp = (float4*)&sW[0][0];
        const float4* srcp = (const float4*)W0;
        #pragma unroll
        for (int r = 0; r < 6; ++r) dstp[tid + r * 256] = srcp[tid + r * 256];
    }
    // stage X tile transposed: sXT[k][m]
    #pragma unroll
    for (int r = 0; r < 12; ++r) {
        int idx = tid + r * 256;      // < 3072
        int m = idx / 48, k = idx - m * 48;
        int n = base + m;
        float v = 0.f;
        if (n < NN) {
            if (k < FIN) v = x[n * 33 + k];
            else {
                int cid = (int)x[n * 33 + FIN];
                v = emb[cid * CDIM + (k - FIN)];
            }
        }
        sXT[k][m] = v;
    }
    // attention vectors for this thread's 8 cols
    float aSr[8], aDr[8];
    #pragma unroll
    for (int j = 0; j < 8; ++j) { aSr[j] = aS0[c * 8 + j]; aDr[j] = aD0[c * 8 + j]; }
    __syncthreads();

    float acc[4][8];
    #pragma unroll
    for (int m = 0; m < 4; ++m)
        #pragma unroll
        for (int j = 0; j < 8; ++j) acc[m][j] = 0.f;

    #pragma unroll 8
    for (int k = 0; k < 48; ++k) {
        float4 wa = *(const float4*)&sW[k][c * 8];
        float4 wb = *(const float4*)&sW[k][c * 8 + 4];
        float xm[4];
        #pragma unroll
        for (int m = 0; m < 4; ++m) xm[m] = sXT[k][rm * 4 + m];
        #pragma unroll
        for (int m = 0; m < 4; ++m) {
            acc[m][0] += xm[m] * wa.x;
            acc[m][1] += xm[m] * wa.y;
            acc[m][2] += xm[m] * wa.z;
            acc[m][3] += xm[m] * wa.w;
            acc[m][4] += xm[m] * wb.x;
            acc[m][5] += xm[m] * wb.y;
            acc[m][6] += xm[m] * wb.z;
            acc[m][7] += xm[m] * wb.w;
        }
    }

    // epilogue: store h0 (fp16) + attention logit partial reduction
    int h = (c >> 3) & 1;             // this thread's cols are entirely in head h
    #pragma unroll
    for (int m = 0; m < 4; ++m) {
        int n = base + rm * 4 + m;
        float vs = 0.f, vd = 0.f;
        #pragma unroll
        for (int j = 0; j < 8; ++j) { vs += acc[m][j] * aSr[j]; vd += acc[m][j] * aDr[j]; }
        // reduce across the 8 threads (one head) of this rowgroup: xor 4,2,1 stays in 8-lane group
        #pragma unroll
        for (int o = 4; o >= 1; o >>= 1) {
            vs += __shfl_xor_sync(0xffffffffu, vs, o);
            vd += __shfl_xor_sync(0xffffffffu, vd, o);
        }
        if (n < NN) {
            __half2 p0 = __floats2half2_rn(acc[m][0], acc[m][1]);
            __half2 p1 = __floats2half2_rn(acc[m][2], acc[m][3]);
            __half2 p2 = __floats2half2_rn(acc[m][4], acc[m][5]);
            __half2 p3 = __floats2half2_rn(acc[m][6], acc[m][7]);
            uint4 u;
            u.x = h2u(p0); u.y = h2u(p1); u.z = h2u(p2); u.w = h2u(p3);
            *(uint4*)&g_h0h[n * 128 + c * 8] = u;
            if ((tid & 7) == 0) {
                g_as0[n * 2 + h] = vs;
                g_ad0[n * 2 + h] = vd;
            }
        }
    }
}

// ---------------- kagg0: layer0 aggregation, warp per dst node --------------------
__global__ void __launch_bounds__(256) kagg0() {
    int w = (blockIdx.x * blockDim.x + threadIdx.x) >> 5;
    if (w >= NN) return;
    int lane = threadIdx.x & 31;
    int start = g_off[w], end = g_off[w + 1];
    float2 ad = *(const float2*)(g_ad0 + w * 2);
    float4 acc = make_float4(0.f, 0.f, 0.f, 0.f);
    float d0 = 0.f, d1 = 0.f;
    for (int i = start; i < end; i += 32) {
        int idx = i + lane;
        int s = 0;
        float ex0 = 0.f, ex1 = 0.f;
        if (idx < end) {
            s = g_srcs[idx];
            float2 a = *(const float2*)(g_as0 + s * 2);
            float v0 = a.x + ad.x;  v0 = v0 > 0.f ? v0 : 0.2f * v0;
            float v1 = a.y + ad.y;  v1 = v1 > 0.f ? v1 : 0.2f * v1;
            ex0 = __expf(v0);
            ex1 = __expf(v1);
        }
        d0 += ex0;
        d1 += ex1;
        int cnt = min(32, end - i);
        #pragma unroll 4
        for (int t = 0; t < cnt; ++t) {
            int sb = __shfl_sync(0xffffffffu, s, t);
            float e0 = __shfl_sync(0xffffffffu, ex0, t);
            float e1 = __shfl_sync(0xffffffffu, ex1, t);
            float exm = (lane < 16) ? e0 : e1;   // lanes 0-15: head0, 16-31: head1
            uint2 p = *(const uint2*)(g_h0h + sb * 128 + lane * 4);
            float2 f01 = __half22float2(*(__half2*)&p.x);
            float2 f23 = __half22float2(*(__half2*)&p.y);
            acc.x += exm * f01.x;
            acc.y += exm * f01.y;
            acc.z += exm * f23.x;
            acc.w += exm * f23.y;
        }
    }
    #pragma unroll
    for (int o = 16; o > 0; o >>= 1) {
        d0 += __shfl_xor_sync(0xffffffffu, d0, o);
        d1 += __shfl_xor_sync(0xffffffffu, d1, o);
    }
    float inv = 1.0f / ((lane < 16) ? d0 : d1);
    acc.x *= inv; acc.y *= inv; acc.z *= inv; acc.w *= inv;
    *(float4*)(g_agg0 + w * 128 + lane * 4) = acc;
}

// ---------------- k4g: fused LN/ELU + tiled GEMM y @ W1 + alpha epilogue -----------
// Block: 256 thr, tile 64 nodes x 64 cols. Thread: 4 nodes x 4 cols.
// Phase A: warp per node (8 warps x 8 nodes): mean-heads+b0, LN, ELU -> sYT.
// Phase B: GEMM. c = tid%16 -> cols c*4.. ; rm = tid/16 -> nodes rm*4..
#define G4_M 64
__global__ void __launch_bounds__(256) k4g(const float* __restrict__ b0,
                   const float* __restrict__ lng, const float* __restrict__ lnb,
                   const float* __restrict__ W1, const float* __restrict__ aS1,
                   const float* __restrict__ aD1) {
    __shared__ float sW1s[64][64];    // 16 KB
    __shared__ float sYT[64][65];     // 16.6 KB, LN(x) transposed
    int tid = threadIdx.x, w = tid >> 5, lane = tid & 31;
    int base = blockIdx.x * G4_M;

    // stage W1 (64x64 row-major)
    {
        float4* dstp = (float4*)&sW1s[0][0];
        const float4* srcp = (const float4*)W1;
        #pragma unroll
        for (int r = 0; r < 4; ++r) dstp[tid + r * 256] = srcp[tid + r * 256];
    }
    // phase A: LN per node; lane owns cols 2*lane, 2*lane+1
    {
        int c2 = lane * 2;
        float2 bb = *(const float2*)&b0[c2];
        float2 gg = *(const float2*)&lng[c2];
        float2 be = *(const float2*)&lnb[c2];
        for (int i = 0; i < 8; ++i) {
            int m = w * 8 + i;
            int n = base + m;
            int nn = (n < NN) ? n : 0;
            float2 a0 = *(const float2*)&g_agg0[nn * 128 + c2];
            float2 a1 = *(const float2*)&g_agg0[nn * 128 + 64 + c2];
            float y0 = 0.5f * (a0.x + a1.x) + bb.x;
            float y1 = 0.5f * (a0.y + a1.y) + bb.y;
            float s1 = y0 + y1, s2 = y0 * y0 + y1 * y1;
            #pragma unroll
            for (int o = 16; o > 0; o >>= 1) {
                s1 += __shfl_xor_sync(0xffffffffu, s1, o);
                s2 += __shfl_xor_sync(0xffffffffu, s2, o);
            }
            float mu = s1 * (1.f / 64.f);
            float var = s2 * (1.f / 64.f) - mu * mu;
            float rstd = rsqrtf(var + 1e-5f);
            float xn0 = (y0 - mu) * rstd * gg.x + be.x;
            float xn1 = (y1 - mu) * rstd * gg.y + be.y;
            float ev0 = xn0 > 0.f ? xn0 : expm1f(xn0);
            float ev1 = xn1 > 0.f ? xn1 : expm1f(xn1);
            sYT[c2][m] = ev0;
            sYT[c2 + 1][m] = ev1;
        }
    }
    int c = tid & 15, rm = tid >> 4;
    float aSr[4], aDr[4];
    #pragma unroll
    for (int j = 0; j < 4; ++j) { aSr[j] = aS1[c * 4 + j]; aDr[j] = aD1[c * 4 + j]; }
    __syncthreads();

    // phase B: GEMM
    float acc[4][4];
    #pragma unroll
    for (int m = 0; m < 4; ++m)
        #pragma unroll
        for (int j = 0; j < 4; ++j) acc[m][j] = 0.f;

    #pragma unroll 8
    for (int k = 0; k < 64; ++k) {
        float4 wa = *(const float4*)&sW1s[k][c * 4];
        float xm[4];
        #pragma unroll
        for (int m = 0; m < 4; ++m) xm[m] = sYT[k][rm * 4 + m];
        #pragma unroll
        for (int m = 0; m < 4; ++m) {
            acc[m][0] += xm[m] * wa.x;
            acc[m][1] += xm[m] * wa.y;
            acc[m][2] += xm[m] * wa.z;
            acc[m][3] += xm[m] * wa.w;
        }
    }

    // epilogue: store h1 (fp16) + alpha reduction across 16 colgroup threads
    #pragma unroll
    for (int m = 0; m < 4; ++m) {
        int n = base + rm * 4 + m;
        float vs = 0.f, vd = 0.f;
        #pragma unroll
        for (int j = 0; j < 4; ++j) { vs += acc[m][j] * aSr[j]; vd += acc[m][j] * aDr[j]; }
        #pragma unroll
        for (int o = 8; o >= 1; o >>= 1) {
            vs += __shfl_xor_sync(0xffffffffu, vs, o);
            vd += __shfl_xor_sync(0xffffffffu, vd, o);
        }
        if (n < NN) {
            __half2 p0 = __floats2half2_rn(acc[m][0], acc[m][1]);
            __half2 p1 = __floats2half2_rn(acc[m][2], acc[m][3]);
            uint2 u;
            u.x = h2u(p0);
            u.y = h2u(p1);
            *(uint2*)&g_h1h[n * 64 + c * 4] = u;
            if ((tid & 15) == 0) {
                g_as1[n] = vs;
                g_ad1[n] = vd;
            }
        }
    }
}

// ---------------- kagg1: layer1 aggregation, warp per dst node, writes out --------
__global__ void __launch_bounds__(256) kagg1(float* __restrict__ out,
                                             const float* __restrict__ b1) {
    int w = (blockIdx.x * blockDim.x + threadIdx.x) >> 5;
    if (w >= NN) return;
    int lane = threadIdx.x & 31;
    int start = g_off[w], end = g_off[w + 1];
    float ad = g_ad1[w];
    float2 acc = make_float2(0.f, 0.f);
    float den = 0.f;
    for (int i = start; i < end; i += 32) {
        int idx = i + lane;
        int s = 0;
        float ex = 0.f;
        if (idx < end) {
            s = g_srcs[idx];
            float v = g_as1[s] + ad;
            v = v > 0.f ? v : 0.2f * v;
            ex = __expf(v);
        }
        den += ex;
        int cnt = min(32, end - i);
        #pragma unroll 4
        for (int t = 0; t < cnt; ++t) {
            int sb = __shfl_sync(0xffffffffu, s, t);
            float eb = __shfl_sync(0xffffffffu, ex, t);
            __half2 hp = *(const __half2*)(g_h1h + sb * 64 + lane * 2);
            float2 f = __half22float2(hp);
            acc.x += eb * f.x;
            acc.y += eb * f.y;
        }
    }
    #pragma unroll
    for (int o = 16; o > 0; o >>= 1)
        den += __shfl_xor_sync(0xffffffffu, den, o);
    float inv = 1.0f / den;
    float2 bb = *(const float2*)(b1 + lane * 2);
    float2 r = make_float2(acc.x * inv + bb.x, acc.y * inv + bb.y);
    *(float2*)(out + w * 64 + lane * 2) = r;
}

// ---------------- launch -----------------------------------------------------------
extern "C" void kernel_launch(void* const* d_in, const int* in_sizes, int n_in,
                              void* d_out, int out_size) {
    const float* x      = (const float*)d_in[0];
    const int*   ei     = (const int*)  d_in[1];
    const float* emb    = (const float*)d_in[2];
    const float* W0     = (const float*)d_in[3];
    const float* a_src0 = (const float*)d_in[4];
    const float* a_dst0 = (const float*)d_in[5];
    const float* b0     = (const float*)d_in[6];
    const float* ln_g   = (const float*)d_in[7];
    const float* ln_b   = (const float*)d_in[8];
    const float* W1     = (const float*)d_in[9];
    const float* a_src1 = (const float*)d_in[10];
    const float* a_dst1 = (const float*)d_in[11];
    const float* b1     = (const float*)d_in[12];
    float* out = (float*)d_out;

    // CSR build (shared by both layers)
    void* cnt_addr = nullptr;
    cudaGetSymbolAddress(&cnt_addr, g_cnt);
    cudaMemsetAsync(cnt_addr, 0, NN * sizeof(int));
    khist<<<(NE + 255) / 256, 256>>>(ei);
    kscan<<<1, 1024>>>();
    kscatter<<<(NE + 255) / 256, 256>>>(ei);
    // layer 0
    k1g<<<(NN + G1_M - 1) / G1_M, 256>>>(x, emb, W0, a_src0, a_dst0);
    kagg0<<<(NN * 32 + 255) / 256, 256>>>();
    // layer 1
    k4g<<<(NN + G4_M - 1) / G4_M, 256>>>(b0, ln_g, ln_b, W1, a_src1, a_dst1);
    kagg1<<<(NN * 32 + 255) / 256, 256>>>(out, b1);
}

// round 16
// speedup vs baseline: 1.3302x; 1.0203x over previous
#include <cuda_runtime.h>
#include <cuda_fp16.h>
#include <math.h>

// Problem constants
#define NN 50000
#define EE 800000
#define NE 850000      // EE + NN self loops
#define FIN 32
#define CDIM 16
#define DIN 48
#define CC 64
#define H0 2

// ---------------- device scratch (allocation-free rule: __device__ globals) --------
__device__ __half g_h0h[NN * 128];    // layer0 node features, fp16 [N,2,64]
__device__ float g_as0[NN * 2];
__device__ float g_ad0[NN * 2];
__device__ float g_agg0[NN * 128];    // normalized aggregated messages (fp32)
__device__ __half g_h1h[NN * 64];     // layer1 input features, fp16
__device__ float g_as1[NN];
__device__ float g_ad1[NN];
// CSR build scratch
__device__ int g_cnt[NN];
__device__ int g_off[NN + 1];
__device__ int g_cur[NN];
__device__ int g_srcs[NE];

__device__ __forceinline__ unsigned h2u(__half2 v) { return *(unsigned*)&v; }

// ---------------- CSR build: histogram of dst -------------------------------------
__global__ void khist(const int* __restrict__ ei) {
    int e = blockIdx.x * blockDim.x + threadIdx.x;
    if (e >= NE) return;
    int dst = (e < EE) ? ei[EE + e] : (e - EE);
    atomicAdd(&g_cnt[dst], 1);
}

// ---------------- CSR build: exclusive scan (single block, 1024 threads) ----------
__global__ void __launch_bounds__(1024) kscan() {
    __shared__ int spart[1024];
    const int CH = (NN + 1023) / 1024;   // 49
    int t = threadIdx.x;
    int base = t * CH;
    int sum = 0;
    for (int i = 0; i < CH; ++i) {
        int b = base + i;
        if (b < NN) sum += g_cnt[b];
    }
    spart[t] = sum;
    __syncthreads();
    for (int o = 1; o < 1024; o <<= 1) {
        int v = (t >= o) ? spart[t - o] : 0;
        __syncthreads();
        spart[t] += v;
        __syncthreads();
    }
    int run = spart[t] - sum;           // exclusive prefix of this thread's chunk
    for (int i = 0; i < CH; ++i) {
        int b = base + i;
        if (b < NN) {
            g_off[b] = run;
            g_cur[b] = run;
            run += g_cnt[b];
        }
    }
    if (t == 1023) g_off[NN] = spart[1023];
}

// ---------------- CSR build: scatter src ids --------------------------------------
__global__ void kscatter(const int* __restrict__ ei) {
    int e = blockIdx.x * blockDim.x + threadIdx.x;
    if (e >= NE) return;
    int src, dst;
    if (e < EE) { src = ei[e]; dst = ei[EE + e]; }
    else        { src = dst = e - EE; }
    int pos = atomicAdd(&g_cur[dst], 1);
    g_srcs[pos] = src;
}

// ---------------- k1g: tiled GEMM  h0 = concat(base,emb) @ W0  + alpha epilogue ----
#define G1_M 64
__global__ void __launch_bounds__(256) k1g(const float* __restrict__ x,
                                           const float* __restrict__ emb,
                                           const float* __restrict__ W0,
                                           const float* __restrict__ aS0,
                                           const float* __restrict__ aD0) {
    __shared__ float sW[48][128];     // 24 KB
    __shared__ float sXT[48][65];     // 12.2 KB, transposed inputs
    int tid = threadIdx.x;
    int c = tid & 15, rm = tid >> 4;
    int base = blockIdx.x * G1_M;

    // stage W0 (48x128, row-major) -> sW
    {
        float4* dstp = (float4*)&sW[0][0];
        const float4* srcp = (const float4*)W0;
        #pragma unroll
        for (int r = 0; r < 6; ++r) dstp[tid + r * 256] = srcp[tid + r * 256];
    }
    // stage X tile transposed: sXT[k][m]
    #pragma unroll
    for (int r = 0; r < 12; ++r) {
        int idx = tid + r * 256;      // < 3072
        int m = idx / 48, k = idx - m * 48;
        int n = base + m;
        float v = 0.f;
        if (n < NN) {
            if (k < FIN) v = x[n * 33 + k];
            else {
                int cid = (int)x[n * 33 + FIN];
                v = emb[cid * CDIM + (k - FIN)];
            }
        }
        sXT[k][m] = v;
    }
    float aSr[8], aDr[8];
    #pragma unroll
    for (int j = 0; j < 8; ++j) { aSr[j] = aS0[c * 8 + j]; aDr[j] = aD0[c * 8 + j]; }
    __syncthreads();

    float acc[4][8];
    #pragma unroll
    for (int m = 0; m < 4; ++m)
        #pragma unroll
        for (int j = 0; j < 8; ++j) acc[m][j] = 0.f;

    #pragma unroll 8
    for (int k = 0; k < 48; ++k) {
        float4 wa = *(const float4*)&sW[k][c * 8];
        float4 wb = *(const float4*)&sW[k][c * 8 + 4];
        float xm[4];
        #pragma unroll
        for (int m = 0; m < 4; ++m) xm[m] = sXT[k][rm * 4 + m];
        #pragma unroll
        for (int m = 0; m < 4; ++m) {
            acc[m][0] += xm[m] * wa.x;
            acc[m][1] += xm[m] * wa.y;
            acc[m][2] += xm[m] * wa.z;
            acc[m][3] += xm[m] * wa.w;
            acc[m][4] += xm[m] * wb.x;
            acc[m][5] += xm[m] * wb.y;
            acc[m][6] += xm[m] * wb.z;
            acc[m][7] += xm[m] * wb.w;
        }
    }

    int h = (c >> 3) & 1;             // this thread's cols are entirely in head h
    #pragma unroll
    for (int m = 0; m < 4; ++m) {
        int n = base + rm * 4 + m;
        float vs = 0.f, vd = 0.f;
        #pragma unroll
        for (int j = 0; j < 8; ++j) { vs += acc[m][j] * aSr[j]; vd += acc[m][j] * aDr[j]; }
        #pragma unroll
        for (int o = 4; o >= 1; o >>= 1) {
            vs += __shfl_xor_sync(0xffffffffu, vs, o);
            vd += __shfl_xor_sync(0xffffffffu, vd, o);
        }
        if (n < NN) {
            __half2 p0 = __floats2half2_rn(acc[m][0], acc[m][1]);
            __half2 p1 = __floats2half2_rn(acc[m][2], acc[m][3]);
            __half2 p2 = __floats2half2_rn(acc[m][4], acc[m][5]);
            __half2 p3 = __floats2half2_rn(acc[m][6], acc[m][7]);
            uint4 u;
            u.x = h2u(p0); u.y = h2u(p1); u.z = h2u(p2); u.w = h2u(p3);
            *(uint4*)&g_h0h[n * 128 + c * 8] = u;
            if ((tid & 7) == 0) {
                g_as0[n * 2 + h] = vs;
                g_ad0[n * 2 + h] = vd;
            }
        }
    }
}

// ---------------- kagg0: layer0 aggregation, warp/dst, 2 edges in flight -----------
// 16 lanes per edge; lane covers cols (lane&15)*8..+7 (uint4 = 8 halfs).
__global__ void __launch_bounds__(256) kagg0() {
    int w = (blockIdx.x * blockDim.x + threadIdx.x) >> 5;
    if (w >= NN) return;
    int lane = threadIdx.x & 31;
    int half = lane >> 4;             // which of the 2 in-flight edges this lane serves
    int lc = lane & 15;               // col group within edge
    int hsel = lc >> 3;               // 0: cols 0-63 (head0), 1: cols 64-127 (head1)
    int start = g_off[w], end = g_off[w + 1];
    float2 ad = *(const float2*)(g_ad0 + w * 2);
    float acc[8];
    #pragma unroll
    for (int j = 0; j < 8; ++j) acc[j] = 0.f;
    float d0 = 0.f, d1 = 0.f;

    for (int i = start; i < end; i += 32) {
        int idx = i + lane;
        int s = 0;
        float ex0 = 0.f, ex1 = 0.f;
        if (idx < end) {
            s = g_srcs[idx];
            float2 a = *(const float2*)(g_as0 + s * 2);
            float v0 = a.x + ad.x;  v0 = v0 > 0.f ? v0 : 0.2f * v0;
            float v1 = a.y + ad.y;  v1 = v1 > 0.f ? v1 : 0.2f * v1;
            ex0 = __expf(v0);
            ex1 = __expf(v1);
        }
        d0 += ex0;
        d1 += ex1;
        int cnt = min(32, end - i);
        #pragma unroll 4
        for (int t = 0; t < cnt; t += 2) {
            int srcl = t + half;      // lower 16 lanes: edge t, upper: edge t+1
            int sb = __shfl_sync(0xffffffffu, s, srcl);
            float e0 = __shfl_sync(0xffffffffu, ex0, srcl);
            float e1 = __shfl_sync(0xffffffffu, ex1, srcl);
            float exm = hsel ? e1 : e0;
            uint4 p = *(const uint4*)(g_h0h + sb * 128 + lc * 8);
            float2 f0 = __half22float2(*(__half2*)&p.x);
            float2 f1 = __half22float2(*(__half2*)&p.y);
            float2 f2 = __half22float2(*(__half2*)&p.z);
            float2 f3 = __half22float2(*(__half2*)&p.w);
            acc[0] += exm * f0.x;  acc[1] += exm * f0.y;
            acc[2] += exm * f1.x;  acc[3] += exm * f1.y;
            acc[4] += exm * f2.x;  acc[5] += exm * f2.y;
            acc[6] += exm * f3.x;  acc[7] += exm * f3.y;
        }
    }
    // combine the two in-flight edge accumulators (halves hold disjoint edge sums)
    #pragma unroll
    for (int j = 0; j < 8; ++j) acc[j] += __shfl_xor_sync(0xffffffffu, acc[j], 16);
    // denominators: full warp reduce
    #pragma unroll
    for (int o = 16; o > 0; o >>= 1) {
        d0 += __shfl_xor_sync(0xffffffffu, d0, o);
        d1 += __shfl_xor_sync(0xffffffffu, d1, o);
    }
    float inv = 1.0f / (hsel ? d1 : d0);
    if (lane < 16) {
        float4 o0 = make_float4(acc[0] * inv, acc[1] * inv, acc[2] * inv, acc[3] * inv);
        float4 o1 = make_float4(acc[4] * inv, acc[5] * inv, acc[6] * inv, acc[7] * inv);
        *(float4*)(g_agg0 + w * 128 + lc * 8) = o0;
        *(float4*)(g_agg0 + w * 128 + lc * 8 + 4) = o1;
    }
}

// ---------------- k4g: fused LN/ELU + tiled GEMM y @ W1 + alpha epilogue -----------
#define G4_M 64
__global__ void __launch_bounds__(256) k4g(const float* __restrict__ b0,
                   const float* __restrict__ lng, const float* __restrict__ lnb,
                   const float* __restrict__ W1, const float* __restrict__ aS1,
                   const float* __restrict__ aD1) {
    __shared__ float sW1s[64][64];    // 16 KB
    __shared__ float sYT[64][65];     // 16.6 KB, LN(x) transposed
    int tid = threadIdx.x, w = tid >> 5, lane = tid & 31;
    int base = blockIdx.x * G4_M;

    {
        float4* dstp = (float4*)&sW1s[0][0];
        const float4* srcp = (const float4*)W1;
        #pragma unroll
        for (int r = 0; r < 4; ++r) dstp[tid + r * 256] = srcp[tid + r * 256];
    }
    // phase A: LN per node; lane owns cols 2*lane, 2*lane+1
    {
        int c2 = lane * 2;
        float2 bb = *(const float2*)&b0[c2];
        float2 gg = *(const float2*)&lng[c2];
        float2 be = *(const float2*)&lnb[c2];
        for (int i = 0; i < 8; ++i) {
            int m = w * 8 + i;
            int n = base + m;
            int nn = (n < NN) ? n : 0;
            float2 a0 = *(const float2*)&g_agg0[nn * 128 + c2];
            float2 a1 = *(const float2*)&g_agg0[nn * 128 + 64 + c2];
            float y0 = 0.5f * (a0.x + a1.x) + bb.x;
            float y1 = 0.5f * (a0.y + a1.y) + bb.y;
            float s1 = y0 + y1, s2 = y0 * y0 + y1 * y1;
            #pragma unroll
            for (int o = 16; o > 0; o >>= 1) {
                s1 += __shfl_xor_sync(0xffffffffu, s1, o);
                s2 += __shfl_xor_sync(0xffffffffu, s2, o);
            }
            float mu = s1 * (1.f / 64.f);
            float var = s2 * (1.f / 64.f) - mu * mu;
            float rstd = rsqrtf(var + 1e-5f);
            float xn0 = (y0 - mu) * rstd * gg.x + be.x;
            float xn1 = (y1 - mu) * rstd * gg.y + be.y;
            float ev0 = xn0 > 0.f ? xn0 : expm1f(xn0);
            float ev1 = xn1 > 0.f ? xn1 : expm1f(xn1);
            sYT[c2][m] = ev0;
            sYT[c2 + 1][m] = ev1;
        }
    }
    int c = tid & 15, rm = tid >> 4;
    float aSr[4], aDr[4];
    #pragma unroll
    for (int j = 0; j < 4; ++j) { aSr[j] = aS1[c * 4 + j]; aDr[j] = aD1[c * 4 + j]; }
    __syncthreads();

    float acc[4][4];
    #pragma unroll
    for (int m = 0; m < 4; ++m)
        #pragma unroll
        for (int j = 0; j < 4; ++j) acc[m][j] = 0.f;

    #pragma unroll 8
    for (int k = 0; k < 64; ++k) {
        float4 wa = *(const float4*)&sW1s[k][c * 4];
        float xm[4];
        #pragma unroll
        for (int m = 0; m < 4; ++m) xm[m] = sYT[k][rm * 4 + m];
        #pragma unroll
        for (int m = 0; m < 4; ++m) {
            acc[m][0] += xm[m] * wa.x;
            acc[m][1] += xm[m] * wa.y;
            acc[m][2] += xm[m] * wa.z;
            acc[m][3] += xm[m] * wa.w;
        }
    }

    #pragma unroll
    for (int m = 0; m < 4; ++m) {
        int n = base + rm * 4 + m;
        float vs = 0.f, vd = 0.f;
        #pragma unroll
        for (int j = 0; j < 4; ++j) { vs += acc[m][j] * aSr[j]; vd += acc[m][j] * aDr[j]; }
        #pragma unroll
        for (int o = 8; o >= 1; o >>= 1) {
            vs += __shfl_xor_sync(0xffffffffu, vs, o);
            vd += __shfl_xor_sync(0xffffffffu, vd, o);
        }
        if (n < NN) {
            __half2 p0 = __floats2half2_rn(acc[m][0], acc[m][1]);
            __half2 p1 = __floats2half2_rn(acc[m][2], acc[m][3]);
            uint2 u;
            u.x = h2u(p0);
            u.y = h2u(p1);
            *(uint2*)&g_h1h[n * 64 + c * 4] = u;
            if ((tid & 15) == 0) {
                g_as1[n] = vs;
                g_ad1[n] = vd;
            }
        }
    }
}

// ---------------- kagg1: layer1 aggregation, warp/dst, 4 edges in flight -----------
// 8 lanes per edge; lane covers cols (lane&7)*8..+7 (uint4 = 8 halfs).
__global__ void __launch_bounds__(256) kagg1(float* __restrict__ out,
                                             const float* __restrict__ b1) {
    int w = (blockIdx.x * blockDim.x + threadIdx.x) >> 5;
    if (w >= NN) return;
    int lane = threadIdx.x & 31;
    int quad = lane >> 3;             // which of the 4 in-flight edges
    int lc = lane & 7;                // col group within edge
    int start = g_off[w], end = g_off[w + 1];
    float ad = g_ad1[w];
    float acc[8];
    #pragma unroll
    for (int j = 0; j < 8; ++j) acc[j] = 0.f;
    float den = 0.f;

    for (int i = start; i < end; i += 32) {
        int idx = i + lane;
        int s = 0;
        float ex = 0.f;
        if (idx < end) {
            s = g_srcs[idx];
            float v = g_as1[s] + ad;
            v = v > 0.f ? v : 0.2f * v;
            ex = __expf(v);
        }
        den += ex;
        int cnt = min(32, end - i);
        #pragma unroll 2
        for (int t = 0; t < cnt; t += 4) {
            int srcl = t + quad;
            int sb = __shfl_sync(0xffffffffu, s, srcl);
            float eb = __shfl_sync(0xffffffffu, ex, srcl);
            uint4 p = *(const uint4*)(g_h1h + sb * 64 + lc * 8);
            float2 f0 = __half22float2(*(__half2*)&p.x);
            float2 f1 = __half22float2(*(__half2*)&p.y);
            float2 f2 = __half22float2(*(__half2*)&p.z);
            float2 f3 = __half22float2(*(__half2*)&p.w);
            acc[0] += eb * f0.x;  acc[1] += eb * f0.y;
            acc[2] += eb * f1.x;  acc[3] += eb * f1.y;
            acc[4] += eb * f2.x;  acc[5] += eb * f2.y;
            acc[6] += eb * f3.x;  acc[7] += eb * f3.y;
        }
    }
    // combine the 4 in-flight edge accumulators
    #pragma unroll
    for (int j = 0; j < 8; ++j) {
        acc[j] += __shfl_xor_sync(0xffffffffu, acc[j], 8);
        acc[j] += __shfl_xor_sync(0xffffffffu, acc[j], 16);
    }
    #pragma unroll
    for (int o = 16; o > 0; o >>= 1)
        den += __shfl_xor_sync(0xffffffffu, den, o);
    float inv = 1.0f / den;
    if (lane < 8) {
        float4 b4a = *(const float4*)&b1[lc * 8];
        float4 b4b = *(const float4*)&b1[lc * 8 + 4];
        float4 o0 = make_float4(acc[0] * inv + b4a.x, acc[1] * inv + b4a.y,
                                acc[2] * inv + b4a.z, acc[3] * inv + b4a.w);
        float4 o1 = make_float4(acc[4] * inv + b4b.x, acc[5] * inv + b4b.y,
                                acc[6] * inv + b4b.z, acc[7] * inv + b4b.w);
        *(float4*)(out + w * 64 + lc * 8) = o0;
        *(float4*)(out + w * 64 + lc * 8 + 4) = o1;
    }
}

// ---------------- launch -----------------------------------------------------------
extern "C" void kernel_launch(void* const* d_in, const int* in_sizes, int n_in,
                              void* d_out, int out_size) {
    const float* x      = (const float*)d_in[0];
    const int*   ei     = (const int*)  d_in[1];
    const float* emb    = (const float*)d_in[2];
    const float* W0     = (const float*)d_in[3];
    const float* a_src0 = (const float*)d_in[4];
    const float* a_dst0 = (const float*)d_in[5];
    const float* b0     = (const float*)d_in[6];
    const float* ln_g   = (const float*)d_in[7];
    const float* ln_b   = (const float*)d_in[8];
    const float* W1     = (const float*)d_in[9];
    const float* a_src1 = (const float*)d_in[10];
    const float* a_dst1 = (const float*)d_in[11];
    const float* b1     = (const float*)d_in[12];
    float* out = (float*)d_out;

    // CSR build (shared by both layers)
    void* cnt_addr = nullptr;
    cudaGetSymbolAddress(&cnt_addr, g_cnt);
    cudaMemsetAsync(cnt_addr, 0, NN * sizeof(int));
    khist<<<(NE + 255) / 256, 256>>>(ei);
    kscan<<<1, 1024>>>();
    kscatter<<<(NE + 255) / 256, 256>>>(ei);
    // layer 0
    k1g<<<(NN + G1_M - 1) / G1_M, 256>>>(x, emb, W0, a_src0, a_dst0);
    kagg0<<<(NN * 32 + 255) / 256, 256>>>();
    // layer 1
    k4g<<<(NN + G4_M - 1) / G4_M, 256>>>(b0, ln_g, ln_b, W1, a_src1, a_dst1);
    kagg1<<<(NN * 32 + 255) / 256, 256>>>(out, b1);
}